// round 10
// baseline (speedup 1.0000x reference)
#include <cuda_runtime.h>
#include <cuda_bf16.h>

#define ALPHA   0.2f
#define NEG_BIG -9.0e15f

#define B_   8
#define N_   2048
#define F_   128
#define S_   4            // j-splits per (batch, i-tile)

typedef unsigned long long u64;
typedef unsigned int u32;

// Scratch (device globals — no allocation allowed in kernel_launch)
__device__ float g_Wh[B_ * N_ * F_];            // fp32, 8 MB (for compute_s)
__device__ __nv_bfloat16 g_Whh[B_ * N_ * F_];   // bf16 hi, 4 MB
__device__ __nv_bfloat16 g_Whl[B_ * N_ * F_];   // bf16 lo (residual), 4 MB
__device__ float g_s1[B_ * N_];
__device__ float g_s2[B_ * N_];
__device__ float g_s2t[N_ * B_];                // transposed s2: [j][b]
__device__ float g_m2[B_ * N_];                 // masked row-max of s2
__device__ u64   g_mask[N_ * (N_ / 64)];        // adjacency bitmask, 512 KB
__device__ float g_pacc[S_ * B_ * N_ * F_];     // partial aggregates, 32 MB
__device__ float g_pl[S_ * B_ * N_];            // partial l sums

// Packed fp32x2 FMA (sm_103a FFMA2): d = a*b + c element-wise.
__device__ __forceinline__ u64 ffma2(u64 a, u64 b, u64 c) {
    u64 d;
    asm("fma.rn.f32x2 %0, %1, %2, %3;" : "=l"(d) : "l"(a), "l"(b), "l"(c));
    return d;
}
__device__ __forceinline__ u64 dup2(float x) {
    u64 d;
    u32 xi = __float_as_uint(x);
    asm("mov.b64 %0, {%1, %2};" : "=l"(d) : "r"(xi), "r"(xi));
    return d;
}

// ldmatrix x4 (non-transposed / transposed)
__device__ __forceinline__ void ldsm4(u32& r0, u32& r1, u32& r2, u32& r3, u32 a) {
    asm volatile("ldmatrix.sync.aligned.m8n8.x4.shared.b16 {%0,%1,%2,%3}, [%4];"
                 : "=r"(r0), "=r"(r1), "=r"(r2), "=r"(r3) : "r"(a));
}
__device__ __forceinline__ void ldsm4t(u32& r0, u32& r1, u32& r2, u32& r3, u32 a) {
    asm volatile("ldmatrix.sync.aligned.m8n8.x4.trans.shared.b16 {%0,%1,%2,%3}, [%4];"
                 : "=r"(r0), "=r"(r1), "=r"(r2), "=r"(r3) : "r"(a));
}

// mma.sync m16n8k16 bf16 -> fp32, D += A*B
__device__ __forceinline__ void mma16816(float* d, u32 a0, u32 a1, u32 a2, u32 a3,
                                         u32 b0, u32 b1) {
    asm volatile(
        "mma.sync.aligned.m16n8k16.row.col.f32.bf16.bf16.f32 "
        "{%0,%1,%2,%3}, {%4,%5,%6,%7}, {%8,%9}, {%0,%1,%2,%3};"
        : "+f"(d[0]), "+f"(d[1]), "+f"(d[2]), "+f"(d[3])
        : "r"(a0), "r"(a1), "r"(a2), "r"(a3), "r"(b0), "r"(b1));
}

// cp.async 16B
__device__ __forceinline__ void cpa16(u32 dst, const void* src) {
    asm volatile("cp.async.cg.shared.global [%0], [%1], 16;"
                 :: "r"(dst), "l"(src));
}

// ---------------------------------------------------------------------------
// Kernel A: Wh = h @ W (FFMA2), 32-row tiles.
// Epilogue writes fp32 + bf16 hi/lo split.
// ---------------------------------------------------------------------------
__global__ void __launch_bounds__(128) wh_gemm(const float* __restrict__ h,
                                               const float* __restrict__ W) {
    __shared__ float hs[32][32];
    __shared__ float Ws[32][128];
    const int tid = threadIdx.x;
    const int tx = tid & 15, ty = tid >> 4;      // ty 0..7, 4 rows each
    const int i0 = blockIdx.x * 32;

    u64 acc[4][4];
    #pragma unroll
    for (int r = 0; r < 4; r++)
        #pragma unroll
        for (int c = 0; c < 4; c++) acc[r][c] = 0ULL;

    for (int k0 = 0; k0 < F_; k0 += 32) {
        #pragma unroll
        for (int p = 0; p < 2; p++) {
            int idx = tid + 128 * p;             // 256 float4
            int r = idx >> 3;
            int c4 = idx & 7;
            *(float4*)&hs[r][c4 * 4] =
                *(const float4*)&h[(i0 + r) * F_ + k0 + c4 * 4];
        }
        #pragma unroll
        for (int p = 0; p < 8; p++) {
            int idx = tid + 128 * p;
            int r = idx >> 5;
            int c4 = idx & 31;
            *(float4*)&Ws[r][c4 * 4] =
                *(const float4*)&W[(k0 + r) * F_ + c4 * 4];
        }
        __syncthreads();
        #pragma unroll
        for (int kk = 0; kk < 32; kk++) {
            u64 av[4];
            #pragma unroll
            for (int r = 0; r < 4; r++) av[r] = dup2(hs[ty * 4 + r][kk]);
            ulonglong2 wa = *(ulonglong2*)&Ws[kk][tx * 8];
            ulonglong2 wb = *(ulonglong2*)&Ws[kk][tx * 8 + 4];
            #pragma unroll
            for (int r = 0; r < 4; r++) {
                acc[r][0] = ffma2(av[r], wa.x, acc[r][0]);
                acc[r][1] = ffma2(av[r], wa.y, acc[r][1]);
                acc[r][2] = ffma2(av[r], wb.x, acc[r][2]);
                acc[r][3] = ffma2(av[r], wb.y, acc[r][3]);
            }
        }
        __syncthreads();
    }
    #pragma unroll
    for (int r = 0; r < 4; r++) {
        int row = i0 + ty * 4 + r;
        float v[8];
        #pragma unroll
        for (int c = 0; c < 4; c++) {
            float2 f = *(float2*)&acc[r][c];
            v[2 * c] = f.x; v[2 * c + 1] = f.y;
        }
        *(float4*)&g_Wh[row * F_ + tx * 8]     = make_float4(v[0], v[1], v[2], v[3]);
        *(float4*)&g_Wh[row * F_ + tx * 8 + 4] = make_float4(v[4], v[5], v[6], v[7]);
        __nv_bfloat162 H[4], L[4];
        #pragma unroll
        for (int c = 0; c < 4; c++) {
            float x = v[2 * c], y = v[2 * c + 1];
            H[c] = __float22bfloat162_rn(make_float2(x, y));
            float lx = x - __low2float(H[c]);
            float ly = y - __high2float(H[c]);
            L[c] = __float22bfloat162_rn(make_float2(lx, ly));
        }
        uint4 uh, ul;
        uh.x = *(u32*)&H[0]; uh.y = *(u32*)&H[1]; uh.z = *(u32*)&H[2]; uh.w = *(u32*)&H[3];
        ul.x = *(u32*)&L[0]; ul.y = *(u32*)&L[1]; ul.z = *(u32*)&L[2]; ul.w = *(u32*)&L[3];
        *(uint4*)&g_Whh[row * F_ + tx * 8] = uh;
        *(uint4*)&g_Whl[row * F_ + tx * 8] = ul;
    }
}

// ---------------------------------------------------------------------------
// Kernel A2: build adjacency bitmask. One warp per row, 16 iterations.
// g_mask[i*32 + w] bit j = (adj[i][w*64 + j] > 0). Only reader of adj.
// ---------------------------------------------------------------------------
__global__ void __launch_bounds__(256) build_mask(const int* __restrict__ adj) {
    const int i = (blockIdx.x * 256 + threadIdx.x) >> 5;     // row
    const int lane = threadIdx.x & 31;
    #pragma unroll 4
    for (int it = 0; it < 16; it++) {
        int j = it * 128 + lane * 4;
        int4 v = *(const int4*)&adj[(long)i * N_ + j];
        u32 nib = (u32)(v.x > 0) | ((u32)(v.y > 0) << 1)
                | ((u32)(v.z > 0) << 2) | ((u32)(v.w > 0) << 3);
        u64 word = (u64)nib << (4 * (lane & 15));
        #pragma unroll
        for (int o = 1; o < 16; o <<= 1)
            word |= __shfl_xor_sync(0xffffffffu, word, o);
        if ((lane & 15) == 0)
            g_mask[i * 32 + it * 2 + (lane >> 4)] = word;
    }
}

// ---------------------------------------------------------------------------
// Kernel B: s1/s2 = Wh·a1 / Wh·a2, plus transposed s2t[j][b].
// ---------------------------------------------------------------------------
__global__ void __launch_bounds__(256) compute_s(const float* __restrict__ a) {
    int row = blockIdx.x * 8 + (threadIdx.x >> 5);
    int lane = threadIdx.x & 31;
    float4 w  = *(const float4*)&g_Wh[row * F_ + lane * 4];
    float4 a1 = *(const float4*)&a[lane * 4];
    float4 a2 = *(const float4*)&a[F_ + lane * 4];
    float d1 = w.x * a1.x + w.y * a1.y + w.z * a1.z + w.w * a1.w;
    float d2 = w.x * a2.x + w.y * a2.y + w.z * a2.z + w.w * a2.w;
    #pragma unroll
    for (int o = 16; o > 0; o >>= 1) {
        d1 += __shfl_xor_sync(0xffffffffu, d1, o);
        d2 += __shfl_xor_sync(0xffffffffu, d2, o);
    }
    if (lane == 0) {
        g_s1[row] = d1;
        g_s2[row] = d2;
        int b = row >> 11;          // N_ = 2048
        int i = row & (N_ - 1);
        g_s2t[i * B_ + b] = d2;
    }
}

// ---------------------------------------------------------------------------
// Kernel B2: m2[b][i] = max over j with adj[i,j]>0 of s2[b][j].
// Mask-driven: lane L owns mask word L (j in [64L, 64L+64)); s2t is 64 KB
// L2-resident. No adj (DRAM) traffic at all.
// ---------------------------------------------------------------------------
__global__ void __launch_bounds__(256) row_max() {
    const int i = blockIdx.x * 8 + (threadIdx.x >> 5);
    const int lane = threadIdx.x & 31;
    float m[8];
    #pragma unroll
    for (int bb = 0; bb < 8; bb++) m[bb] = NEG_BIG;

    const u64 word = g_mask[i * 32 + lane];
    const float* s2b = g_s2t + lane * 64 * B_;
    #pragma unroll 4
    for (int jj = 0; jj < 64; jj++) {
        if ((word >> jj) & 1ULL) {
            float4 v0 = *(const float4*)&s2b[jj * B_];
            float4 v1 = *(const float4*)&s2b[jj * B_ + 4];
            m[0] = fmaxf(m[0], v0.x); m[1] = fmaxf(m[1], v0.y);
            m[2] = fmaxf(m[2], v0.z); m[3] = fmaxf(m[3], v0.w);
            m[4] = fmaxf(m[4], v1.x); m[5] = fmaxf(m[5], v1.y);
            m[6] = fmaxf(m[6], v1.z); m[7] = fmaxf(m[7], v1.w);
        }
    }
    #pragma unroll
    for (int o = 16; o > 0; o >>= 1)
        #pragma unroll
        for (int bb = 0; bb < 8; bb++)
            m[bb] = fmaxf(m[bb], __shfl_xor_sync(0xffffffffu, m[bb], o));
    if (lane == 0) {
        #pragma unroll
        for (int bb = 0; bb < 8; bb++) g_m2[bb * N_ + i] = m[bb];
    }
}

// ---------------------------------------------------------------------------
// Kernel C: split-j masked softmax aggregation, mma.sync bf16x3.
// Pipelined: cp.async WT fills overlap the score phase; adjacency via
// L2-resident bitmask (broadcast u64 loads).
//
// smem layout (bytes), strides padded for conflict-free ldmatrix:
//   WThi [64][136 bf16] stride 272B  @ 0      (17408)
//   WTlo                              @ 17408 (17408)
//   Phi  [64][72 bf16]  stride 144B  @ 34816 (9216)
//   Plo                               @ 44032 (9216)
//   s1s/Ms fp32[64]                   @ 53248/53504
// ---------------------------------------------------------------------------
#define OFF_WTHI 0
#define OFF_WTLO 17408
#define OFF_PHI  34816
#define OFF_PLO  44032
#define OFF_S1   53248
#define OFF_MS   53504
#define SMEM_C   53760

__global__ void __launch_bounds__(128, 4) gat_attn() {
    extern __shared__ char smc[];
    float* s1s = (float*)(smc + OFF_S1);
    float* Ms  = (float*)(smc + OFF_MS);

    const int tid = threadIdx.x;
    const int lane = tid & 31;
    const int w = tid >> 5;                      // warp 0..3
    const int b = blockIdx.y;
    const int s = blockIdx.z;
    const int i0 = blockIdx.x * 64;

    const u32 sbase = (u32)__cvta_generic_to_shared(smc);

    if (tid < 64) {
        float s1 = g_s1[b * N_ + i0 + tid];
        float m2 = g_m2[b * N_ + i0 + tid];
        s1s[tid] = s1;
        float Mi;
        if (m2 < -8.0e15f) {
            Mi = NEG_BIG;                        // empty row -> uniform softmax
        } else {
            float x = s1 + m2;
            Mi = fmaxf(x, ALPHA * x);            // lr monotone -> row max
        }
        Ms[tid] = Mi;
    }
    __syncthreads();

    float acc[4][4][4];                          // [m-tile][n8][quad]
    #pragma unroll
    for (int m = 0; m < 4; m++)
        #pragma unroll
        for (int n = 0; n < 4; n++)
            #pragma unroll
            for (int c = 0; c < 4; c++) acc[m][n][c] = 0.f;
    float lacc[8];                               // row-sum partials, row g+8k
    #pragma unroll
    for (int k = 0; k < 8; k++) lacc[k] = 0.f;

    const int g  = tid >> 4;                     // 0..7: score-phase row group
    const int jq = (tid & 15) * 4;               // score-phase j quad

    // ldmatrix lane-invariant offsets
    const int lg = lane >> 3, lr = lane & 7;
    const u32 aoff = (u32)(((lg & 1) * 8 + lr) * 144 + (lg >> 1) * 16);
    const u32 boff = (u32)(((lg & 1) * 8 + lr) * 272 + (lg >> 1) * 16);

    const int jt0 = s * (N_ / 64 / S_);          // 8 tiles per split
    const int jt1 = jt0 + (N_ / 64 / S_);

    for (int jt = jt0; jt < jt1; jt++) {
        const int j0 = jt * 64;

        // ---- issue async WT fills (overlap with score phase) ----
        {
            const uint4* srcH = (const uint4*)&g_Whh[(b * N_ + j0) * F_];
            const uint4* srcL = (const uint4*)&g_Whl[(b * N_ + j0) * F_];
            #pragma unroll
            for (int p = 0; p < 8; p++) {
                int idx = tid + 128 * p;         // 1024 uint4 (64 rows x 16)
                int r = idx >> 4;
                int c16 = idx & 15;
                u32 doff = (u32)(r * 272 + c16 * 16);
                cpa16(sbase + OFF_WTHI + doff, srcH + r * 16 + c16);
                cpa16(sbase + OFF_WTLO + doff, srcL + r * 16 + c16);
            }
            asm volatile("cp.async.commit_group;");
        }

        // ---- scores + exp + bf16 hi/lo split + register l-sums ----
        {
            // mask words: broadcast across 16-lane groups, L2-resident
            u64 mw[8];
            #pragma unroll
            for (int k = 0; k < 8; k++)
                mw[k] = g_mask[(i0 + g + 8 * k) * 32 + jt];
            float4 s2v = *(const float4*)&g_s2[b * N_ + j0 + jq];
            #pragma unroll
            for (int k = 0; k < 8; k++) {
                int i = g + 8 * k;
                u32 nib = (u32)(mw[k] >> jq) & 15u;
                float s1v = s1s[i];
                float Mi  = Ms[i];
                float x0 = s1v + s2v.x, x1 = s1v + s2v.y;
                float x2 = s1v + s2v.z, x3 = s1v + s2v.w;
                float l0 = fmaxf(x0, ALPHA * x0), l1 = fmaxf(x1, ALPHA * x1);
                float l2 = fmaxf(x2, ALPHA * x2), l3 = fmaxf(x3, ALPHA * x3);
                float p0 = __expf(((nib & 1u) ? l0 : NEG_BIG) - Mi);
                float p1 = __expf(((nib & 2u) ? l1 : NEG_BIG) - Mi);
                float p2 = __expf(((nib & 4u) ? l2 : NEG_BIG) - Mi);
                float p3 = __expf(((nib & 8u) ? l3 : NEG_BIG) - Mi);
                lacc[k] += (p0 + p1) + (p2 + p3);
                __nv_bfloat162 h01 = __float22bfloat162_rn(make_float2(p0, p1));
                __nv_bfloat162 h23 = __float22bfloat162_rn(make_float2(p2, p3));
                float q0 = p0 - __low2float(h01),  q1 = p1 - __high2float(h01);
                float q2 = p2 - __low2float(h23),  q3 = p3 - __high2float(h23);
                __nv_bfloat162 l01 = __float22bfloat162_rn(make_float2(q0, q1));
                __nv_bfloat162 l23 = __float22bfloat162_rn(make_float2(q2, q3));
                uint2 uh, ulv;
                uh.x = *(u32*)&h01; uh.y = *(u32*)&h23;
                ulv.x = *(u32*)&l01; ulv.y = *(u32*)&l23;
                *(uint2*)(smc + OFF_PHI + i * 144 + jq * 2) = uh;
                *(uint2*)(smc + OFF_PLO + i * 144 + jq * 2) = ulv;
            }
        }

        asm volatile("cp.async.wait_group 0;");
        __syncthreads();

        // ---- aggregation: P(64x64) @ Wh(64x128), N-split warps ----
        {
            #pragma unroll
            for (int ks = 0; ks < 4; ks++) {
                // B fragments for this warp's 32-col strip (2 n16 groups)
                u32 bh[2][4], bl[2][4];
                const u32 bbase = sbase + OFF_WTHI + (u32)(ks * 16 * 272)
                                + boff + (u32)(w * 64);
                #pragma unroll
                for (int ng = 0; ng < 2; ng++) {
                    u32 bb = bbase + ng * 32;
                    ldsm4t(bh[ng][0], bh[ng][1], bh[ng][2], bh[ng][3], bb);
                    ldsm4t(bl[ng][0], bl[ng][1], bl[ng][2], bl[ng][3],
                           bb + (OFF_WTLO - OFF_WTHI));
                }
                #pragma unroll
                for (int m = 0; m < 4; m++) {
                    u32 ah0, ah1, ah2, ah3, al0, al1, al2, al3;
                    u32 aA = sbase + OFF_PHI + (u32)(m * 16 * 144) + aoff
                           + (u32)(ks * 32);
                    ldsm4(ah0, ah1, ah2, ah3, aA);
                    ldsm4(al0, al1, al2, al3, aA + (OFF_PLO - OFF_PHI));
                    #pragma unroll
                    for (int ng = 0; ng < 2; ng++) {
                        mma16816(acc[m][2 * ng],     ah0, ah1, ah2, ah3, bh[ng][0], bh[ng][1]);
                        mma16816(acc[m][2 * ng],     ah0, ah1, ah2, ah3, bl[ng][0], bl[ng][1]);
                        mma16816(acc[m][2 * ng],     al0, al1, al2, al3, bh[ng][0], bh[ng][1]);
                        mma16816(acc[m][2 * ng + 1], ah0, ah1, ah2, ah3, bh[ng][2], bh[ng][3]);
                        mma16816(acc[m][2 * ng + 1], ah0, ah1, ah2, ah3, bl[ng][2], bl[ng][3]);
                        mma16816(acc[m][2 * ng + 1], al0, al1, al2, al3, bh[ng][2], bh[ng][3]);
                    }
                }
            }
        }
        __syncthreads();
    }

    // ---- partial l: reduce lacc over the 16-lane row groups ----
    #pragma unroll
    for (int k = 0; k < 8; k++) {
        float v = lacc[k];
        v += __shfl_xor_sync(0xffffffffu, v, 1);
        v += __shfl_xor_sync(0xffffffffu, v, 2);
        v += __shfl_xor_sync(0xffffffffu, v, 4);
        v += __shfl_xor_sync(0xffffffffu, v, 8);
        if ((tid & 15) == 0)
            g_pl[(s * B_ + b) * N_ + i0 + g + 8 * k] = v;
    }

    // ---- partial accumulator (unnormalized) ----
    {
        float* pout = g_pacc + ((long)(s * B_ + b) * N_ + i0) * F_;
        const int rr = lane >> 2;
        const int c0 = w * 32 + 2 * (lane & 3);
        #pragma unroll
        for (int m = 0; m < 4; m++) {
            #pragma unroll
            for (int gq = 0; gq < 4; gq++) {
                int row0 = 16 * m + rr;
                int col = c0 + 8 * gq;
                *(float2*)&pout[row0 * F_ + col] =
                    make_float2(acc[m][gq][0], acc[m][gq][1]);
                *(float2*)&pout[(row0 + 8) * F_ + col] =
                    make_float2(acc[m][gq][2], acc[m][gq][3]);
            }
        }
    }
}

// ---------------------------------------------------------------------------
// Kernel D: reduce splits. out[b,i,f] = sum_s pacc / sum_s pl.
// ---------------------------------------------------------------------------
__global__ void __launch_bounds__(256) reduce_splits(float* __restrict__ out) {
    const long idx = (long)blockIdx.x * 256 + threadIdx.x;   // float4 index
    const long row = idx >> 5;                               // F_/4 = 32 per row
    const long NBF = (long)B_ * N_ * F_ / 4;                 // float4 per split

    float l = 0.f;
    #pragma unroll
    for (int s = 0; s < S_; s++) l += g_pl[s * B_ * N_ + row];
    float inv = 1.f / l;

    float4 acc = make_float4(0.f, 0.f, 0.f, 0.f);
    const float4* pa = (const float4*)g_pacc;
    #pragma unroll
    for (int s = 0; s < S_; s++) {
        float4 v = pa[s * NBF + idx];
        acc.x += v.x; acc.y += v.y; acc.z += v.z; acc.w += v.w;
    }
    float4 o = make_float4(acc.x * inv, acc.y * inv, acc.z * inv, acc.w * inv);
    ((float4*)out)[idx] = o;
}

// ---------------------------------------------------------------------------
extern "C" void kernel_launch(void* const* d_in, const int* in_sizes, int n_in,
                              void* d_out, int out_size) {
    const float* h   = (const float*)d_in[0];   // [8,2048,128]
    const int*   adj = (const int*)d_in[1];     // [2048,2048]
    const float* W   = (const float*)d_in[2];   // [128,128]
    const float* a   = (const float*)d_in[3];   // [256,1]
    float* out = (float*)d_out;                 // [8,2048,128]

    (void)in_sizes; (void)n_in; (void)out_size;

    static bool attr_set = false;
    if (!attr_set) {
        cudaFuncSetAttribute(gat_attn,
                             cudaFuncAttributeMaxDynamicSharedMemorySize,
                             SMEM_C);
        attr_set = true;
    }

    wh_gemm<<<(B_ * N_) / 32, 128>>>(h, W);
    build_mask<<<N_ / 8, 256>>>(adj);
    compute_s<<<(B_ * N_) / 8, 256>>>(a);
    row_max<<<N_ / 8, 256>>>();
    gat_attn<<<dim3(N_ / 64, B_, S_), 128, SMEM_C>>>();
    reduce_splits<<<(B_ * N_ * F_ / 4) / 256, 256>>>(out);
}

// round 11
// speedup vs baseline: 1.1324x; 1.1324x over previous
#include <cuda_runtime.h>
#include <cuda_bf16.h>

#define ALPHA   0.2f
#define NEG_BIG -9.0e15f

#define B_   8
#define N_   2048
#define F_   128
#define S_   4            // j-splits per (batch, i-tile)

typedef unsigned long long u64;
typedef unsigned int u32;

// Scratch (device globals — no allocation allowed in kernel_launch)
__device__ float g_Wh[B_ * N_ * F_];            // fp32, 8 MB (for compute_s)
__device__ __nv_bfloat16 g_Whh[B_ * N_ * F_];   // bf16 hi, 4 MB
__device__ __nv_bfloat16 g_Whl[B_ * N_ * F_];   // bf16 lo (residual), 4 MB
__device__ float g_s1[B_ * N_];
__device__ float g_s2[B_ * N_];
__device__ float g_gmax[B_];                    // global max of s2 per batch
__device__ u32   g_nonempty[N_];                // per-row has-any-neighbor flag
__device__ u64   g_mask[N_ * (N_ / 64)];        // adjacency bitmask, 512 KB
__device__ float g_pacc[S_ * B_ * N_ * F_];     // partial aggregates, 32 MB
__device__ float g_pl[S_ * B_ * N_];            // partial l sums

// Packed fp32x2 FMA (sm_103a FFMA2): d = a*b + c element-wise.
__device__ __forceinline__ u64 ffma2(u64 a, u64 b, u64 c) {
    u64 d;
    asm("fma.rn.f32x2 %0, %1, %2, %3;" : "=l"(d) : "l"(a), "l"(b), "l"(c));
    return d;
}
__device__ __forceinline__ u64 dup2(float x) {
    u64 d;
    u32 xi = __float_as_uint(x);
    asm("mov.b64 %0, {%1, %2};" : "=l"(d) : "r"(xi), "r"(xi));
    return d;
}

// ldmatrix x4 (non-transposed / transposed)
__device__ __forceinline__ void ldsm4(u32& r0, u32& r1, u32& r2, u32& r3, u32 a) {
    asm volatile("ldmatrix.sync.aligned.m8n8.x4.shared.b16 {%0,%1,%2,%3}, [%4];"
                 : "=r"(r0), "=r"(r1), "=r"(r2), "=r"(r3) : "r"(a));
}
__device__ __forceinline__ void ldsm4t(u32& r0, u32& r1, u32& r2, u32& r3, u32 a) {
    asm volatile("ldmatrix.sync.aligned.m8n8.x4.trans.shared.b16 {%0,%1,%2,%3}, [%4];"
                 : "=r"(r0), "=r"(r1), "=r"(r2), "=r"(r3) : "r"(a));
}

// mma.sync m16n8k16 bf16 -> fp32, D += A*B
__device__ __forceinline__ void mma16816(float* d, u32 a0, u32 a1, u32 a2, u32 a3,
                                         u32 b0, u32 b1) {
    asm volatile(
        "mma.sync.aligned.m16n8k16.row.col.f32.bf16.bf16.f32 "
        "{%0,%1,%2,%3}, {%4,%5,%6,%7}, {%8,%9}, {%0,%1,%2,%3};"
        : "+f"(d[0]), "+f"(d[1]), "+f"(d[2]), "+f"(d[3])
        : "r"(a0), "r"(a1), "r"(a2), "r"(a3), "r"(b0), "r"(b1));
}

// cp.async 16B
__device__ __forceinline__ void cpa16(u32 dst, const void* src) {
    asm volatile("cp.async.cg.shared.global [%0], [%1], 16;"
                 :: "r"(dst), "l"(src));
}

// ---------------------------------------------------------------------------
// Kernel A: Wh = h @ W (FFMA2), 32-row tiles.
// Epilogue writes fp32 + bf16 hi/lo split.
// ---------------------------------------------------------------------------
__global__ void __launch_bounds__(128) wh_gemm(const float* __restrict__ h,
                                               const float* __restrict__ W) {
    __shared__ float hs[32][32];
    __shared__ float Ws[32][128];
    const int tid = threadIdx.x;
    const int tx = tid & 15, ty = tid >> 4;      // ty 0..7, 4 rows each
    const int i0 = blockIdx.x * 32;

    u64 acc[4][4];
    #pragma unroll
    for (int r = 0; r < 4; r++)
        #pragma unroll
        for (int c = 0; c < 4; c++) acc[r][c] = 0ULL;

    for (int k0 = 0; k0 < F_; k0 += 32) {
        #pragma unroll
        for (int p = 0; p < 2; p++) {
            int idx = tid + 128 * p;             // 256 float4
            int r = idx >> 3;
            int c4 = idx & 7;
            *(float4*)&hs[r][c4 * 4] =
                *(const float4*)&h[(i0 + r) * F_ + k0 + c4 * 4];
        }
        #pragma unroll
        for (int p = 0; p < 8; p++) {
            int idx = tid + 128 * p;
            int r = idx >> 5;
            int c4 = idx & 31;
            *(float4*)&Ws[r][c4 * 4] =
                *(const float4*)&W[(k0 + r) * F_ + c4 * 4];
        }
        __syncthreads();
        #pragma unroll
        for (int kk = 0; kk < 32; kk++) {
            u64 av[4];
            #pragma unroll
            for (int r = 0; r < 4; r++) av[r] = dup2(hs[ty * 4 + r][kk]);
            ulonglong2 wa = *(ulonglong2*)&Ws[kk][tx * 8];
            ulonglong2 wb = *(ulonglong2*)&Ws[kk][tx * 8 + 4];
            #pragma unroll
            for (int r = 0; r < 4; r++) {
                acc[r][0] = ffma2(av[r], wa.x, acc[r][0]);
                acc[r][1] = ffma2(av[r], wa.y, acc[r][1]);
                acc[r][2] = ffma2(av[r], wb.x, acc[r][2]);
                acc[r][3] = ffma2(av[r], wb.y, acc[r][3]);
            }
        }
        __syncthreads();
    }
    #pragma unroll
    for (int r = 0; r < 4; r++) {
        int row = i0 + ty * 4 + r;
        float v[8];
        #pragma unroll
        for (int c = 0; c < 4; c++) {
            float2 f = *(float2*)&acc[r][c];
            v[2 * c] = f.x; v[2 * c + 1] = f.y;
        }
        *(float4*)&g_Wh[row * F_ + tx * 8]     = make_float4(v[0], v[1], v[2], v[3]);
        *(float4*)&g_Wh[row * F_ + tx * 8 + 4] = make_float4(v[4], v[5], v[6], v[7]);
        __nv_bfloat162 H[4], L[4];
        #pragma unroll
        for (int c = 0; c < 4; c++) {
            float x = v[2 * c], y = v[2 * c + 1];
            H[c] = __float22bfloat162_rn(make_float2(x, y));
            float lx = x - __low2float(H[c]);
            float ly = y - __high2float(H[c]);
            L[c] = __float22bfloat162_rn(make_float2(lx, ly));
        }
        uint4 uh, ul;
        uh.x = *(u32*)&H[0]; uh.y = *(u32*)&H[1]; uh.z = *(u32*)&H[2]; uh.w = *(u32*)&H[3];
        ul.x = *(u32*)&L[0]; ul.y = *(u32*)&L[1]; ul.z = *(u32*)&L[2]; ul.w = *(u32*)&L[3];
        *(uint4*)&g_Whh[row * F_ + tx * 8] = uh;
        *(uint4*)&g_Whl[row * F_ + tx * 8] = ul;
    }
}

// ---------------------------------------------------------------------------
// Kernel A2: build adjacency bitmask + per-row nonempty flag.
// One warp per row. Only reader of adj.
// ---------------------------------------------------------------------------
__global__ void __launch_bounds__(256) build_mask(const int* __restrict__ adj) {
    const int i = (blockIdx.x * 256 + threadIdx.x) >> 5;     // row
    const int lane = threadIdx.x & 31;
    u32 rowany = 0;
    #pragma unroll 4
    for (int it = 0; it < 16; it++) {
        int j = it * 128 + lane * 4;
        int4 v = *(const int4*)&adj[(long)i * N_ + j];
        u32 nib = (u32)(v.x > 0) | ((u32)(v.y > 0) << 1)
                | ((u32)(v.z > 0) << 2) | ((u32)(v.w > 0) << 3);
        rowany |= nib;
        u64 word = (u64)nib << (4 * (lane & 15));
        #pragma unroll
        for (int o = 1; o < 16; o <<= 1)
            word |= __shfl_xor_sync(0xffffffffu, word, o);
        if ((lane & 15) == 0)
            g_mask[i * 32 + it * 2 + (lane >> 4)] = word;
    }
    u32 ne = __any_sync(0xffffffffu, rowany != 0) ? 1u : 0u;
    if (lane == 0) g_nonempty[i] = ne;
}

// ---------------------------------------------------------------------------
// Kernel B: s1/s2 = Wh·a1 / Wh·a2.
// ---------------------------------------------------------------------------
__global__ void __launch_bounds__(256) compute_s(const float* __restrict__ a) {
    int row = blockIdx.x * 8 + (threadIdx.x >> 5);
    int lane = threadIdx.x & 31;
    float4 w  = *(const float4*)&g_Wh[row * F_ + lane * 4];
    float4 a1 = *(const float4*)&a[lane * 4];
    float4 a2 = *(const float4*)&a[F_ + lane * 4];
    float d1 = w.x * a1.x + w.y * a1.y + w.z * a1.z + w.w * a1.w;
    float d2 = w.x * a2.x + w.y * a2.y + w.z * a2.z + w.w * a2.w;
    #pragma unroll
    for (int o = 16; o > 0; o >>= 1) {
        d1 += __shfl_xor_sync(0xffffffffu, d1, o);
        d2 += __shfl_xor_sync(0xffffffffu, d2, o);
    }
    if (lane == 0) {
        g_s1[row] = d1;
        g_s2[row] = d2;
    }
}

// ---------------------------------------------------------------------------
// Kernel B2: g_gmax[b] = max_j s2[b][j]. One CTA per batch.
// (Softmax is shift-invariant: any M >= masked row max - ~80 is numerically
//  safe, so the batch-global unmasked max replaces the per-row masked max.)
// ---------------------------------------------------------------------------
__global__ void __launch_bounds__(256) gmax_s2() {
    __shared__ float wmax[8];
    const int b = blockIdx.x;
    const int tid = threadIdx.x;
    float m = NEG_BIG;
    #pragma unroll
    for (int k = 0; k < N_ / 256; k++)
        m = fmaxf(m, g_s2[b * N_ + k * 256 + tid]);
    #pragma unroll
    for (int o = 16; o > 0; o >>= 1)
        m = fmaxf(m, __shfl_xor_sync(0xffffffffu, m, o));
    if ((tid & 31) == 0) wmax[tid >> 5] = m;
    __syncthreads();
    if (tid < 8) {
        m = wmax[tid];
        #pragma unroll
        for (int o = 4; o > 0; o >>= 1)
            m = fmaxf(m, __shfl_xor_sync(0xffu, m, o));
        if (tid == 0) g_gmax[b] = m;
    }
}

// ---------------------------------------------------------------------------
// Kernel C: split-j masked softmax aggregation, mma.sync bf16x3.
// Pipelined: cp.async WT fills overlap the score phase; adjacency via
// L2-resident bitmask (broadcast u64 loads).
//
// smem layout (bytes), strides padded for conflict-free ldmatrix:
//   WThi [64][136 bf16] stride 272B  @ 0      (17408)
//   WTlo                              @ 17408 (17408)
//   Phi  [64][72 bf16]  stride 144B  @ 34816 (9216)
//   Plo                               @ 44032 (9216)
//   s1s/Ms fp32[64]                   @ 53248/53504
// ---------------------------------------------------------------------------
#define OFF_WTHI 0
#define OFF_WTLO 17408
#define OFF_PHI  34816
#define OFF_PLO  44032
#define OFF_S1   53248
#define OFF_MS   53504
#define SMEM_C   53760

__global__ void __launch_bounds__(128, 4) gat_attn() {
    extern __shared__ char smc[];
    float* s1s = (float*)(smc + OFF_S1);
    float* Ms  = (float*)(smc + OFF_MS);

    const int tid = threadIdx.x;
    const int lane = tid & 31;
    const int w = tid >> 5;                      // warp 0..3
    const int b = blockIdx.y;
    const int s = blockIdx.z;
    const int i0 = blockIdx.x * 64;

    const u32 sbase = (u32)__cvta_generic_to_shared(smc);

    if (tid < 64) {
        float s1 = g_s1[b * N_ + i0 + tid];
        u32 ne = g_nonempty[i0 + tid];
        s1s[tid] = s1;
        float x = s1 + g_gmax[b];
        float Mi = ne ? fmaxf(x, ALPHA * x) : NEG_BIG;
        Ms[tid] = Mi;
    }
    __syncthreads();

    float acc[4][4][4];                          // [m-tile][n8][quad]
    #pragma unroll
    for (int m = 0; m < 4; m++)
        #pragma unroll
        for (int n = 0; n < 4; n++)
            #pragma unroll
            for (int c = 0; c < 4; c++) acc[m][n][c] = 0.f;
    float lacc[8];                               // row-sum partials, row g+8k
    #pragma unroll
    for (int k = 0; k < 8; k++) lacc[k] = 0.f;

    const int g  = tid >> 4;                     // 0..7: score-phase row group
    const int jq = (tid & 15) * 4;               // score-phase j quad

    // ldmatrix lane-invariant offsets
    const int lg = lane >> 3, lr = lane & 7;
    const u32 aoff = (u32)(((lg & 1) * 8 + lr) * 144 + (lg >> 1) * 16);
    const u32 boff = (u32)(((lg & 1) * 8 + lr) * 272 + (lg >> 1) * 16);

    const int jt0 = s * (N_ / 64 / S_);          // 8 tiles per split
    const int jt1 = jt0 + (N_ / 64 / S_);

    for (int jt = jt0; jt < jt1; jt++) {
        const int j0 = jt * 64;

        // ---- issue async WT fills (overlap with score phase) ----
        {
            const uint4* srcH = (const uint4*)&g_Whh[(b * N_ + j0) * F_];
            const uint4* srcL = (const uint4*)&g_Whl[(b * N_ + j0) * F_];
            #pragma unroll
            for (int p = 0; p < 8; p++) {
                int idx = tid + 128 * p;         // 1024 uint4 (64 rows x 16)
                int r = idx >> 4;
                int c16 = idx & 15;
                u32 doff = (u32)(r * 272 + c16 * 16);
                cpa16(sbase + OFF_WTHI + doff, srcH + r * 16 + c16);
                cpa16(sbase + OFF_WTLO + doff, srcL + r * 16 + c16);
            }
            asm volatile("cp.async.commit_group;");
        }

        // ---- scores + exp + bf16 hi/lo split + register l-sums ----
        {
            // mask words: broadcast across 16-lane groups, L2-resident
            u64 mw[8];
            #pragma unroll
            for (int k = 0; k < 8; k++)
                mw[k] = g_mask[(i0 + g + 8 * k) * 32 + jt];
            float4 s2v = *(const float4*)&g_s2[b * N_ + j0 + jq];
            #pragma unroll
            for (int k = 0; k < 8; k++) {
                int i = g + 8 * k;
                u32 nib = (u32)(mw[k] >> jq) & 15u;
                float s1v = s1s[i];
                float Mi  = Ms[i];
                float x0 = s1v + s2v.x, x1 = s1v + s2v.y;
                float x2 = s1v + s2v.z, x3 = s1v + s2v.w;
                float l0 = fmaxf(x0, ALPHA * x0), l1 = fmaxf(x1, ALPHA * x1);
                float l2 = fmaxf(x2, ALPHA * x2), l3 = fmaxf(x3, ALPHA * x3);
                float p0 = __expf(((nib & 1u) ? l0 : NEG_BIG) - Mi);
                float p1 = __expf(((nib & 2u) ? l1 : NEG_BIG) - Mi);
                float p2 = __expf(((nib & 4u) ? l2 : NEG_BIG) - Mi);
                float p3 = __expf(((nib & 8u) ? l3 : NEG_BIG) - Mi);
                lacc[k] += (p0 + p1) + (p2 + p3);
                __nv_bfloat162 h01 = __float22bfloat162_rn(make_float2(p0, p1));
                __nv_bfloat162 h23 = __float22bfloat162_rn(make_float2(p2, p3));
                float q0 = p0 - __low2float(h01),  q1 = p1 - __high2float(h01);
                float q2 = p2 - __low2float(h23),  q3 = p3 - __high2float(h23);
                __nv_bfloat162 l01 = __float22bfloat162_rn(make_float2(q0, q1));
                __nv_bfloat162 l23 = __float22bfloat162_rn(make_float2(q2, q3));
                uint2 uh, ulv;
                uh.x = *(u32*)&h01; uh.y = *(u32*)&h23;
                ulv.x = *(u32*)&l01; ulv.y = *(u32*)&l23;
                *(uint2*)(smc + OFF_PHI + i * 144 + jq * 2) = uh;
                *(uint2*)(smc + OFF_PLO + i * 144 + jq * 2) = ulv;
            }
        }

        asm volatile("cp.async.wait_group 0;");
        __syncthreads();

        // ---- aggregation: P(64x64) @ Wh(64x128), N-split warps ----
        {
            #pragma unroll
            for (int ks = 0; ks < 4; ks++) {
                // B fragments for this warp's 32-col strip (2 n16 groups)
                u32 bh[2][4], bl[2][4];
                const u32 bbase = sbase + OFF_WTHI + (u32)(ks * 16 * 272)
                                + boff + (u32)(w * 64);
                #pragma unroll
                for (int ng = 0; ng < 2; ng++) {
                    u32 bb = bbase + ng * 32;
                    ldsm4t(bh[ng][0], bh[ng][1], bh[ng][2], bh[ng][3], bb);
                    ldsm4t(bl[ng][0], bl[ng][1], bl[ng][2], bl[ng][3],
                           bb + (OFF_WTLO - OFF_WTHI));
                }
                #pragma unroll
                for (int m = 0; m < 4; m++) {
                    u32 ah0, ah1, ah2, ah3, al0, al1, al2, al3;
                    u32 aA = sbase + OFF_PHI + (u32)(m * 16 * 144) + aoff
                           + (u32)(ks * 32);
                    ldsm4(ah0, ah1, ah2, ah3, aA);
                    ldsm4(al0, al1, al2, al3, aA + (OFF_PLO - OFF_PHI));
                    #pragma unroll
                    for (int ng = 0; ng < 2; ng++) {
                        mma16816(acc[m][2 * ng],     ah0, ah1, ah2, ah3, bh[ng][0], bh[ng][1]);
                        mma16816(acc[m][2 * ng],     ah0, ah1, ah2, ah3, bl[ng][0], bl[ng][1]);
                        mma16816(acc[m][2 * ng],     al0, al1, al2, al3, bh[ng][0], bh[ng][1]);
                        mma16816(acc[m][2 * ng + 1], ah0, ah1, ah2, ah3, bh[ng][2], bh[ng][3]);
                        mma16816(acc[m][2 * ng + 1], ah0, ah1, ah2, ah3, bl[ng][2], bl[ng][3]);
                        mma16816(acc[m][2 * ng + 1], al0, al1, al2, al3, bh[ng][2], bh[ng][3]);
                    }
                }
            }
        }
        __syncthreads();
    }

    // ---- partial l: reduce lacc over the 16-lane row groups ----
    #pragma unroll
    for (int k = 0; k < 8; k++) {
        float v = lacc[k];
        v += __shfl_xor_sync(0xffffffffu, v, 1);
        v += __shfl_xor_sync(0xffffffffu, v, 2);
        v += __shfl_xor_sync(0xffffffffu, v, 4);
        v += __shfl_xor_sync(0xffffffffu, v, 8);
        if ((tid & 15) == 0)
            g_pl[(s * B_ + b) * N_ + i0 + g + 8 * k] = v;
    }

    // ---- partial accumulator (unnormalized) ----
    {
        float* pout = g_pacc + ((long)(s * B_ + b) * N_ + i0) * F_;
        const int rr = lane >> 2;
        const int c0 = w * 32 + 2 * (lane & 3);
        #pragma unroll
        for (int m = 0; m < 4; m++) {
            #pragma unroll
            for (int gq = 0; gq < 4; gq++) {
                int row0 = 16 * m + rr;
                int col = c0 + 8 * gq;
                *(float2*)&pout[row0 * F_ + col] =
                    make_float2(acc[m][gq][0], acc[m][gq][1]);
                *(float2*)&pout[(row0 + 8) * F_ + col] =
                    make_float2(acc[m][gq][2], acc[m][gq][3]);
            }
        }
    }
}

// ---------------------------------------------------------------------------
// Kernel D: reduce splits. out[b,i,f] = sum_s pacc / sum_s pl.
// ---------------------------------------------------------------------------
__global__ void __launch_bounds__(256) reduce_splits(float* __restrict__ out) {
    const long idx = (long)blockIdx.x * 256 + threadIdx.x;   // float4 index
    const long row = idx >> 5;                               // F_/4 = 32 per row
    const long NBF = (long)B_ * N_ * F_ / 4;                 // float4 per split

    float l = 0.f;
    #pragma unroll
    for (int s = 0; s < S_; s++) l += g_pl[s * B_ * N_ + row];
    float inv = 1.f / l;

    float4 acc = make_float4(0.f, 0.f, 0.f, 0.f);
    const float4* pa = (const float4*)g_pacc;
    #pragma unroll
    for (int s = 0; s < S_; s++) {
        float4 v = pa[s * NBF + idx];
        acc.x += v.x; acc.y += v.y; acc.z += v.z; acc.w += v.w;
    }
    float4 o = make_float4(acc.x * inv, acc.y * inv, acc.z * inv, acc.w * inv);
    ((float4*)out)[idx] = o;
}

// ---------------------------------------------------------------------------
extern "C" void kernel_launch(void* const* d_in, const int* in_sizes, int n_in,
                              void* d_out, int out_size) {
    const float* h   = (const float*)d_in[0];   // [8,2048,128]
    const int*   adj = (const int*)d_in[1];     // [2048,2048]
    const float* W   = (const float*)d_in[2];   // [128,128]
    const float* a   = (const float*)d_in[3];   // [256,1]
    float* out = (float*)d_out;                 // [8,2048,128]

    (void)in_sizes; (void)n_in; (void)out_size;

    static bool attr_set = false;
    if (!attr_set) {
        cudaFuncSetAttribute(gat_attn,
                             cudaFuncAttributeMaxDynamicSharedMemorySize,
                             SMEM_C);
        attr_set = true;
    }

    wh_gemm<<<(B_ * N_) / 32, 128>>>(h, W);
    build_mask<<<N_ / 8, 256>>>(adj);
    compute_s<<<(B_ * N_) / 8, 256>>>(a);
    gmax_s2<<<B_, 256>>>();
    gat_attn<<<dim3(N_ / 64, B_, S_), 128, SMEM_C>>>();
    reduce_splits<<<(B_ * N_ * F_ / 4) / 256, 256>>>(out);
}

// round 14
// speedup vs baseline: 1.6422x; 1.4502x over previous
#include <cuda_runtime.h>
#include <cuda_bf16.h>
#include <cuda_fp16.h>

#define ALPHA   0.2f
#define NEG_BIG -9.0e15f

#define B_   8
#define N_   2048
#define F_   128
#define S_   4            // j-splits per (batch, i-tile)

typedef unsigned long long u64;
typedef unsigned int u32;

// Scratch (device globals — no allocation allowed in kernel_launch)
__device__ float g_Wh[B_ * N_ * F_];            // fp32, 8 MB (for compute_s)
__device__ __half g_Whh[B_ * N_ * F_];          // fp16, 4 MB (MMA operand)
__device__ float g_s1[B_ * N_];
__device__ float g_s2[B_ * N_];
__device__ float g_gmax[B_];                    // global max of s2 per batch
__device__ u32   g_nonempty[N_];                // per-row has-any-neighbor flag
__device__ u64   g_mask[N_ * (N_ / 64)];        // adjacency bitmask, 512 KB
__device__ float g_pacc[S_ * B_ * N_ * F_];     // partial aggregates, 32 MB
__device__ float g_pl[S_ * B_ * N_];            // partial l sums

// Packed fp32x2 FMA (sm_103a FFMA2): d = a*b + c element-wise.
__device__ __forceinline__ u64 ffma2(u64 a, u64 b, u64 c) {
    u64 d;
    asm("fma.rn.f32x2 %0, %1, %2, %3;" : "=l"(d) : "l"(a), "l"(b), "l"(c));
    return d;
}
__device__ __forceinline__ u64 dup2(float x) {
    u64 d;
    u32 xi = __float_as_uint(x);
    asm("mov.b64 %0, {%1, %2};" : "=l"(d) : "r"(xi), "r"(xi));
    return d;
}

// ldmatrix x4 (non-transposed / transposed)
__device__ __forceinline__ void ldsm4(u32& r0, u32& r1, u32& r2, u32& r3, u32 a) {
    asm volatile("ldmatrix.sync.aligned.m8n8.x4.shared.b16 {%0,%1,%2,%3}, [%4];"
                 : "=r"(r0), "=r"(r1), "=r"(r2), "=r"(r3) : "r"(a));
}
__device__ __forceinline__ void ldsm4t(u32& r0, u32& r1, u32& r2, u32& r3, u32 a) {
    asm volatile("ldmatrix.sync.aligned.m8n8.x4.trans.shared.b16 {%0,%1,%2,%3}, [%4];"
                 : "=r"(r0), "=r"(r1), "=r"(r2), "=r"(r3) : "r"(a));
}

// mma.sync m16n8k16 fp16 -> fp32, D += A*B
__device__ __forceinline__ void mma16816(float* d, u32 a0, u32 a1, u32 a2, u32 a3,
                                         u32 b0, u32 b1) {
    asm volatile(
        "mma.sync.aligned.m16n8k16.row.col.f32.f16.f16.f32 "
        "{%0,%1,%2,%3}, {%4,%5,%6,%7}, {%8,%9}, {%0,%1,%2,%3};"
        : "+f"(d[0]), "+f"(d[1]), "+f"(d[2]), "+f"(d[3])
        : "r"(a0), "r"(a1), "r"(a2), "r"(a3), "r"(b0), "r"(b1));
}

// cp.async 16B
__device__ __forceinline__ void cpa16(u32 dst, const void* src) {
    asm volatile("cp.async.cg.shared.global [%0], [%1], 16;"
                 :: "r"(dst), "l"(src));
}

// float atomicMax via sign-aware integer atomics
__device__ __forceinline__ void atomicMaxFloat(float* addr, float value) {
    if (value >= 0.f)
        atomicMax((int*)addr, __float_as_int(value));
    else
        atomicMin((unsigned int*)addr, (unsigned int)__float_as_int(value));
}

// ---------------------------------------------------------------------------
// Kernel A: Wh = h @ W (FFMA2), 32-row tiles.
// Epilogue writes fp32 + fp16 copy.
// ---------------------------------------------------------------------------
__global__ void __launch_bounds__(128) wh_gemm(const float* __restrict__ h,
                                               const float* __restrict__ W) {
    __shared__ float hs[32][32];
    __shared__ float Ws[32][128];
    const int tid = threadIdx.x;
    const int tx = tid & 15, ty = tid >> 4;      // ty 0..7, 4 rows each
    const int i0 = blockIdx.x * 32;

    u64 acc[4][4];
    #pragma unroll
    for (int r = 0; r < 4; r++)
        #pragma unroll
        for (int c = 0; c < 4; c++) acc[r][c] = 0ULL;

    for (int k0 = 0; k0 < F_; k0 += 32) {
        #pragma unroll
        for (int p = 0; p < 2; p++) {
            int idx = tid + 128 * p;             // 256 float4
            int r = idx >> 3;
            int c4 = idx & 7;
            *(float4*)&hs[r][c4 * 4] =
                *(const float4*)&h[(i0 + r) * F_ + k0 + c4 * 4];
        }
        #pragma unroll
        for (int p = 0; p < 8; p++) {
            int idx = tid + 128 * p;
            int r = idx >> 5;
            int c4 = idx & 31;
            *(float4*)&Ws[r][c4 * 4] =
                *(const float4*)&W[(k0 + r) * F_ + c4 * 4];
        }
        __syncthreads();
        #pragma unroll
        for (int kk = 0; kk < 32; kk++) {
            u64 av[4];
            #pragma unroll
            for (int r = 0; r < 4; r++) av[r] = dup2(hs[ty * 4 + r][kk]);
            ulonglong2 wa = *(ulonglong2*)&Ws[kk][tx * 8];
            ulonglong2 wb = *(ulonglong2*)&Ws[kk][tx * 8 + 4];
            #pragma unroll
            for (int r = 0; r < 4; r++) {
                acc[r][0] = ffma2(av[r], wa.x, acc[r][0]);
                acc[r][1] = ffma2(av[r], wa.y, acc[r][1]);
                acc[r][2] = ffma2(av[r], wb.x, acc[r][2]);
                acc[r][3] = ffma2(av[r], wb.y, acc[r][3]);
            }
        }
        __syncthreads();
    }
    #pragma unroll
    for (int r = 0; r < 4; r++) {
        int row = i0 + ty * 4 + r;
        float v[8];
        #pragma unroll
        for (int c = 0; c < 4; c++) {
            float2 f = *(float2*)&acc[r][c];
            v[2 * c] = f.x; v[2 * c + 1] = f.y;
        }
        *(float4*)&g_Wh[row * F_ + tx * 8]     = make_float4(v[0], v[1], v[2], v[3]);
        *(float4*)&g_Wh[row * F_ + tx * 8 + 4] = make_float4(v[4], v[5], v[6], v[7]);
        __half2 H[4];
        #pragma unroll
        for (int c = 0; c < 4; c++)
            H[c] = __float22half2_rn(make_float2(v[2 * c], v[2 * c + 1]));
        uint4 uh;
        uh.x = *(u32*)&H[0]; uh.y = *(u32*)&H[1];
        uh.z = *(u32*)&H[2]; uh.w = *(u32*)&H[3];
        *(uint4*)&g_Whh[row * F_ + tx * 8] = uh;
    }
}

// ---------------------------------------------------------------------------
// Kernel A2: build adjacency bitmask + per-row nonempty flag + gmax init.
// One warp per row. Only reader of adj.
// ---------------------------------------------------------------------------
__global__ void __launch_bounds__(256) build_mask(const int* __restrict__ adj) {
    if (blockIdx.x == 0 && threadIdx.x < B_) g_gmax[threadIdx.x] = NEG_BIG;
    const int i = (blockIdx.x * 256 + threadIdx.x) >> 5;     // row
    const int lane = threadIdx.x & 31;
    u32 rowany = 0;
    #pragma unroll 4
    for (int it = 0; it < 16; it++) {
        int j = it * 128 + lane * 4;
        int4 v = *(const int4*)&adj[(long)i * N_ + j];
        u32 nib = (u32)(v.x > 0) | ((u32)(v.y > 0) << 1)
                | ((u32)(v.z > 0) << 2) | ((u32)(v.w > 0) << 3);
        rowany |= nib;
        u64 word = (u64)nib << (4 * (lane & 15));
        #pragma unroll
        for (int o = 1; o < 16; o <<= 1)
            word |= __shfl_xor_sync(0xffffffffu, word, o);
        if ((lane & 15) == 0)
            g_mask[i * 32 + it * 2 + (lane >> 4)] = word;
    }
    u32 ne = __any_sync(0xffffffffu, rowany != 0) ? 1u : 0u;
    if (lane == 0) g_nonempty[i] = ne;
}

// ---------------------------------------------------------------------------
// Kernel B: s1/s2 = Wh·a1 / Wh·a2, fused batch-global s2 max (atomic).
// Block = 8 consecutive rows (same batch: 2048 % 8 == 0).
// ---------------------------------------------------------------------------
__global__ void __launch_bounds__(256) compute_s(const float* __restrict__ a) {
    __shared__ float s2sh[8];
    int row = blockIdx.x * 8 + (threadIdx.x >> 5);
    int lane = threadIdx.x & 31;
    float4 w  = *(const float4*)&g_Wh[row * F_ + lane * 4];
    float4 a1 = *(const float4*)&a[lane * 4];
    float4 a2 = *(const float4*)&a[F_ + lane * 4];
    float d1 = w.x * a1.x + w.y * a1.y + w.z * a1.z + w.w * a1.w;
    float d2 = w.x * a2.x + w.y * a2.y + w.z * a2.z + w.w * a2.w;
    #pragma unroll
    for (int o = 16; o > 0; o >>= 1) {
        d1 += __shfl_xor_sync(0xffffffffu, d1, o);
        d2 += __shfl_xor_sync(0xffffffffu, d2, o);
    }
    if (lane == 0) {
        g_s1[row] = d1;
        g_s2[row] = d2;
        s2sh[threadIdx.x >> 5] = d2;
    }
    __syncthreads();
    if (threadIdx.x < 8) {
        float v = s2sh[threadIdx.x];
        #pragma unroll
        for (int o = 4; o > 0; o >>= 1)
            v = fmaxf(v, __shfl_xor_sync(0xffu, v, o));
        if (threadIdx.x == 0)
            atomicMaxFloat(&g_gmax[(blockIdx.x * 8) >> 11], v);
    }
}

// ---------------------------------------------------------------------------
// Kernel C: split-j masked softmax aggregation, mma.sync fp16 (single term;
// fp16's 11-bit mantissa + fp32 accum gives ~3e-4 rel err, 3x under bound).
// Pipelined: cp.async WT fill overlaps the score phase; adjacency via
// L2-resident bitmask (broadcast u64 loads).
//
// smem layout (bytes), strides padded for conflict-free ldmatrix:
//   WT [64][136 fp16] stride 272B  @ 0      (17408)
//   P  [64][72 fp16]  stride 144B  @ 17408  (9216)
//   s1s/Ms fp32[64]                @ 26624/26880
// ---------------------------------------------------------------------------
#define OFF_WT  0
#define OFF_P   17408
#define OFF_S1  26624
#define OFF_MS  26880
#define SMEM_C  27136

__global__ void __launch_bounds__(128, 4) gat_attn() {
    extern __shared__ char smc[];
    float* s1s = (float*)(smc + OFF_S1);
    float* Ms  = (float*)(smc + OFF_MS);

    const int tid = threadIdx.x;
    const int lane = tid & 31;
    const int w = tid >> 5;                      // warp 0..3
    const int b = blockIdx.y;
    const int s = blockIdx.z;
    const int i0 = blockIdx.x * 64;

    const u32 sbase = (u32)__cvta_generic_to_shared(smc);

    if (tid < 64) {
        float s1 = g_s1[b * N_ + i0 + tid];
        u32 ne = g_nonempty[i0 + tid];
        s1s[tid] = s1;
        float x = s1 + g_gmax[b];
        float Mi = ne ? fmaxf(x, ALPHA * x) : NEG_BIG;
        Ms[tid] = Mi;
    }
    __syncthreads();

    float acc[4][4][4];                          // [m-tile][n8][quad]
    #pragma unroll
    for (int m = 0; m < 4; m++)
        #pragma unroll
        for (int n = 0; n < 4; n++)
            #pragma unroll
            for (int c = 0; c < 4; c++) acc[m][n][c] = 0.f;
    float lacc[8];                               // row-sum partials, row g+8k
    #pragma unroll
    for (int k = 0; k < 8; k++) lacc[k] = 0.f;

    const int g  = tid >> 4;                     // 0..7: score-phase row group
    const int jq = (tid & 15) * 4;               // score-phase j quad

    // ldmatrix lane-invariant offsets
    const int lg = lane >> 3, lr = lane & 7;
    const u32 aoff = (u32)(((lg & 1) * 8 + lr) * 144 + (lg >> 1) * 16);
    const u32 boff = (u32)(((lg & 1) * 8 + lr) * 272 + (lg >> 1) * 16);

    const int jt0 = s * (N_ / 64 / S_);          // 8 tiles per split
    const int jt1 = jt0 + (N_ / 64 / S_);

    for (int jt = jt0; jt < jt1; jt++) {
        const int j0 = jt * 64;

        // ---- issue async WT fill (overlaps the score phase) ----
        {
            const uint4* srcH = (const uint4*)&g_Whh[(b * N_ + j0) * F_];
            #pragma unroll
            for (int p = 0; p < 8; p++) {
                int idx = tid + 128 * p;         // 1024 uint4 (64 rows x 16)
                int r = idx >> 4;
                int c16 = idx & 15;
                cpa16(sbase + OFF_WT + (u32)(r * 272 + c16 * 16),
                      srcH + r * 16 + c16);
            }
            asm volatile("cp.async.commit_group;");
        }

        // ---- scores + exp + fp16 pack + register l-sums ----
        {
            // mask words: broadcast across 16-lane groups, L2-resident
            u64 mw[8];
            #pragma unroll
            for (int k = 0; k < 8; k++)
                mw[k] = g_mask[(i0 + g + 8 * k) * 32 + jt];
            float4 s2v = *(const float4*)&g_s2[b * N_ + j0 + jq];
            #pragma unroll
            for (int k = 0; k < 8; k++) {
                int i = g + 8 * k;
                u32 nib = (u32)(mw[k] >> jq) & 15u;
                float s1v = s1s[i];
                float Mi  = Ms[i];
                float x0 = s1v + s2v.x, x1 = s1v + s2v.y;
                float x2 = s1v + s2v.z, x3 = s1v + s2v.w;
                float l0 = fmaxf(x0, ALPHA * x0), l1 = fmaxf(x1, ALPHA * x1);
                float l2 = fmaxf(x2, ALPHA * x2), l3 = fmaxf(x3, ALPHA * x3);
                float p0 = __expf(((nib & 1u) ? l0 : NEG_BIG) - Mi);
                float p1 = __expf(((nib & 2u) ? l1 : NEG_BIG) - Mi);
                float p2 = __expf(((nib & 4u) ? l2 : NEG_BIG) - Mi);
                float p3 = __expf(((nib & 8u) ? l3 : NEG_BIG) - Mi);
                lacc[k] += (p0 + p1) + (p2 + p3);
                __half2 h01 = __float22half2_rn(make_float2(p0, p1));
                __half2 h23 = __float22half2_rn(make_float2(p2, p3));
                uint2 uh;
                uh.x = *(u32*)&h01; uh.y = *(u32*)&h23;
                *(uint2*)(smc + OFF_P + i * 144 + jq * 2) = uh;
            }
        }

        asm volatile("cp.async.wait_group 0;");
        __syncthreads();

        // ---- aggregation: P(64x64) @ Wh(64x128), N-split warps, fp16 ----
        {
            #pragma unroll
            for (int ks = 0; ks < 4; ks++) {
                // B fragments for this warp's 32-col strip (2 n16 groups)
                u32 bh[2][4];
                const u32 bbase = sbase + OFF_WT + (u32)(ks * 16 * 272)
                                + boff + (u32)(w * 64);
                #pragma unroll
                for (int ng = 0; ng < 2; ng++)
                    ldsm4t(bh[ng][0], bh[ng][1], bh[ng][2], bh[ng][3],
                           bbase + ng * 32);
                #pragma unroll
                for (int m = 0; m < 4; m++) {
                    u32 ah0, ah1, ah2, ah3;
                    ldsm4(ah0, ah1, ah2, ah3,
                          sbase + OFF_P + (u32)(m * 16 * 144) + aoff
                          + (u32)(ks * 32));
                    #pragma unroll
                    for (int ng = 0; ng < 2; ng++) {
                        mma16816(acc[m][2 * ng],     ah0, ah1, ah2, ah3,
                                 bh[ng][0], bh[ng][1]);
                        mma16816(acc[m][2 * ng + 1], ah0, ah1, ah2, ah3,
                                 bh[ng][2], bh[ng][3]);
                    }
                }
            }
        }
        __syncthreads();
    }

    // ---- partial l: reduce lacc over the 16-lane row groups ----
    #pragma unroll
    for (int k = 0; k < 8; k++) {
        float v = lacc[k];
        v += __shfl_xor_sync(0xffffffffu, v, 1);
        v += __shfl_xor_sync(0xffffffffu, v, 2);
        v += __shfl_xor_sync(0xffffffffu, v, 4);
        v += __shfl_xor_sync(0xffffffffu, v, 8);
        if ((tid & 15) == 0)
            g_pl[(s * B_ + b) * N_ + i0 + g + 8 * k] = v;
    }

    // ---- partial accumulator (unnormalized) ----
    {
        float* pout = g_pacc + ((long)(s * B_ + b) * N_ + i0) * F_;
        const int rr = lane >> 2;
        const int c0 = w * 32 + 2 * (lane & 3);
        #pragma unroll
        for (int m = 0; m < 4; m++) {
            #pragma unroll
            for (int gq = 0; gq < 4; gq++) {
                int row0 = 16 * m + rr;
                int col = c0 + 8 * gq;
                *(float2*)&pout[row0 * F_ + col] =
                    make_float2(acc[m][gq][0], acc[m][gq][1]);
                *(float2*)&pout[(row0 + 8) * F_ + col] =
                    make_float2(acc[m][gq][2], acc[m][gq][3]);
            }
        }
    }
}

// ---------------------------------------------------------------------------
// Kernel D: reduce splits. out[b,i,f] = sum_s pacc / sum_s pl.
// ---------------------------------------------------------------------------
__global__ void __launch_bounds__(256) reduce_splits(float* __restrict__ out) {
    const long idx = (long)blockIdx.x * 256 + threadIdx.x;   // float4 index
    const long row = idx >> 5;                               // F_/4 = 32 per row
    const long NBF = (long)B_ * N_ * F_ / 4;                 // float4 per split

    float l = 0.f;
    #pragma unroll
    for (int s = 0; s < S_; s++) l += g_pl[s * B_ * N_ + row];
    float inv = 1.f / l;

    float4 acc = make_float4(0.f, 0.f, 0.f, 0.f);
    const float4* pa = (const float4*)g_pacc;
    #pragma unroll
    for (int s = 0; s < S_; s++) {
        float4 v = pa[s * NBF + idx];
        acc.x += v.x; acc.y += v.y; acc.z += v.z; acc.w += v.w;
    }
    float4 o = make_float4(acc.x * inv, acc.y * inv, acc.z * inv, acc.w * inv);
    ((float4*)out)[idx] = o;
}

// ---------------------------------------------------------------------------
extern "C" void kernel_launch(void* const* d_in, const int* in_sizes, int n_in,
                              void* d_out, int out_size) {
    const float* h   = (const float*)d_in[0];   // [8,2048,128]
    const int*   adj = (const int*)d_in[1];     // [2048,2048]
    const float* W   = (const float*)d_in[2];   // [128,128]
    const float* a   = (const float*)d_in[3];   // [256,1]
    float* out = (float*)d_out;                 // [8,2048,128]

    (void)in_sizes; (void)n_in; (void)out_size;

    static bool attr_set = false;
    if (!attr_set) {
        cudaFuncSetAttribute(gat_attn,
                             cudaFuncAttributeMaxDynamicSharedMemorySize,
                             SMEM_C);
        attr_set = true;
    }

    wh_gemm<<<(B_ * N_) / 32, 128>>>(h, W);
    build_mask<<<N_ / 8, 256>>>(adj);
    compute_s<<<(B_ * N_) / 8, 256>>>(a);
    gat_attn<<<dim3(N_ / 64, B_, S_), 128, SMEM_C>>>();
    reduce_splits<<<(B_ * N_ * F_ / 4) / 256, 256>>>(out);
}